// round 15
// baseline (speedup 1.0000x reference)
#include <cuda_runtime.h>
#include <math.h>

#define T_MAXC 1000000
#define THR 256
#define WARPS (THR / 32)                    // 8
#define NB 444                              // scan blocks (=148*3, co-resident @3/SM)
#define U4PL 3                              // uint4 per lane
#define U4PW (U4PL * 32)                    // 96 uint4 per warp
#define CHUNK (U4PW * 4 * WARPS)            // 3072 buckets per block
#define T_PAD (NB * CHUNK)                  // 1363968 (padding stays 0)
#define FPS 2048.0f                         // 2^11 fixed-point scale
#define INV_FPS_F (1.0f / 2048.0f)
#define EMASK 0x00FFFFFFu
#define DESC_FLAG (1ULL << 63)

typedef unsigned long long u64;
typedef unsigned int u32;

// Static device globals (zero at load; every launch restores zeros).
// Packed bucket: bits[0:24) sum(exp x) in 2^-11 fixed point, bits[24:32) event count.
__device__ u32 g_packed[T_PAD];
__device__ volatile u64 g_desc[NB];         // chunk aggregate | DESC_FLAG when valid
__device__ double g_evx;
__device__ double g_logterm;
__device__ u32 g_cnt;

// ---------------------------------------------------------------------------
__device__ __forceinline__ double block_reduce_f64(double v, double* shw) {
    int lane = threadIdx.x & 31, wid = threadIdx.x >> 5;
#pragma unroll
    for (int s = 16; s > 0; s >>= 1) v += __shfl_down_sync(0xFFFFFFFFu, v, s);
    if (lane == 0) shw[wid] = v;
    __syncthreads();
    double t = 0.0;
    if (threadIdx.x == 0)
#pragma unroll
        for (int w = 0; w < WARPS; w++) t += shw[w];
    return t;  // valid on tid 0
}

// ---------------------------------------------------------------------------
// Pass 1: one u32 RED per element (sumexp fixed-point + event count packed).
__device__ __forceinline__ void proc(float xv, float tv, float ev, float& evx) {
    int ti = (int)tv;
    ti = min(max(ti, 0), T_MAXC - 1);
    u32 enc = __float2uint_rn(__expf(xv) * FPS) + ((u32)ev << 24);
    atomicAdd(&g_packed[ti], enc);
    if (ev != 0.0f) evx += xv;              // float partial; double at block reduce
}

__global__ void __launch_bounds__(THR) accum_kernel(const float* __restrict__ x,
                                                    const float* __restrict__ tgt,
                                                    int n) {
    const float4* x4 = reinterpret_cast<const float4*>(x);
    const float4* t4 = reinterpret_cast<const float4*>(tgt);
    int n8 = n >> 3;
    int stride = gridDim.x * blockDim.x;
    float evx = 0.0f;

    for (int i = blockIdx.x * blockDim.x + threadIdx.x; i < n8; i += stride) {
        // front-batched streaming loads: 8 elements per iteration
        float4 xa = __ldcg(&x4[2 * i]);
        float4 xb = __ldcg(&x4[2 * i + 1]);
        float4 t0 = __ldcg(&t4[4 * i]);
        float4 t1 = __ldcg(&t4[4 * i + 1]);
        float4 t2 = __ldcg(&t4[4 * i + 2]);
        float4 t3 = __ldcg(&t4[4 * i + 3]);
        proc(xa.x, t0.x, t0.y, evx);
        proc(xa.y, t0.z, t0.w, evx);
        proc(xa.z, t1.x, t1.y, evx);
        proc(xa.w, t1.z, t1.w, evx);
        proc(xb.x, t2.x, t2.y, evx);
        proc(xb.y, t2.z, t2.w, evx);
        proc(xb.z, t3.x, t3.y, evx);
        proc(xb.w, t3.z, t3.w, evx);
    }
    if (blockIdx.x == 0 && threadIdx.x == 0) {           // scalar tail
        for (int i = n8 * 8; i < n; i++)
            proc(x[i], tgt[2 * i], tgt[2 * i + 1], evx);
    }

    __shared__ double shd[WARPS];
    double t = block_reduce_f64((double)evx, shd);
    if (threadIdx.x == 0) atomicAdd(&g_evx, t);
}

// ---------------------------------------------------------------------------
// Pass 2: single-wave suffix scan, warp-interleaved ownership, decoupled
// aggregate lookback. NB=444 = 148*3 blocks co-resident (3 blocks/SM at
// <=85 regs, ~100B smem) -> spin is deadlock-free.
__global__ void __launch_bounds__(THR, 3) scan_kernel(float* __restrict__ out, int n) {
    __shared__ u64 shw[WARPS];      // per-warp totals (live whole kernel)
    __shared__ u64 sh2[WARPS];      // lookback reduction scratch
    __shared__ double shd[WARPS];
    __shared__ u64 sh_look;
    __shared__ bool is_last;

    int tid = threadIdx.x, b = blockIdx.x;
    int lane = tid & 31, wid = tid >> 5;

    // --- coalesced direct loads: lane k owns uint4 (base + j*32 + k) ---
    uint4* p4 = reinterpret_cast<uint4*>(g_packed);
    int base = b * (CHUNK / 4) + wid * U4PW + lane;
    uint4 r[U4PL];
    u32 s[U4PL];
    u32 local = 0;
#pragma unroll
    for (int j = 0; j < U4PL; j++) {
        r[j] = p4[base + j * 32];
        s[j] = (r[j].x & EMASK) + (r[j].y & EMASK) +
               (r[j].z & EMASK) + (r[j].w & EMASK);
        local += s[j];
    }
#pragma unroll
    for (int j = 0; j < U4PL; j++)
        p4[base + j * 32] = make_uint4(0u, 0u, 0u, 0u);   // re-zero for next launch

    // --- warp totals -> block aggregate -> publish (single u64 word) ---
    u32 lv = local;
#pragma unroll
    for (int st = 16; st > 0; st >>= 1) lv += __shfl_down_sync(0xFFFFFFFFu, lv, st);
    if (lane == 0) shw[wid] = (u64)lv;
    __syncthreads();
    if (tid == 0) {
        u64 t = 0;
#pragma unroll
        for (int w = 0; w < WARPS; w++) t += shw[w];
        g_desc[b] = t | DESC_FLAG;
    }

    // --- lookback: spin-read later chunk aggregates in parallel ---
    u64 lb = 0;
    for (int jj = b + 1 + tid; jj < NB; jj += THR) {
        u64 d;
        do { d = g_desc[jj]; } while (!(d & DESC_FLAG));
        lb += d & ~DESC_FLAG;
    }
#pragma unroll
    for (int st = 16; st > 0; st >>= 1) lb += __shfl_down_sync(0xFFFFFFFFu, lb, st);
    if (lane == 0) sh2[wid] = lb;
    __syncthreads();
    if (tid == 0) {
        u64 t = 0;
#pragma unroll
        for (int w = 0; w < WARPS; w++) t += sh2[w];
        sh_look = t;
    }
    __syncthreads();

    // --- exclusive suffix base for this warp ---
    u64 woff = 0;
#pragma unroll
    for (int w = 0; w < WARPS; w++)
        if (w > wid) woff += shw[w];
    u64 run_base = sh_look + woff;   // sum of everything after this warp's range

    // --- per-j warp suffix scans interleaved with log walk (float run) ---
    float contrib = 0.0f;
#pragma unroll
    for (int j = U4PL - 1; j >= 0; j--) {
        u32 v = s[j];
#pragma unroll
        for (int st = 1; st < 32; st <<= 1) {
            u32 o = __shfl_down_sync(0xFFFFFFFFu, v, st);
            if (lane + st < 32) v += o;
        }
        u32 total = __shfl_sync(0xFFFFFFFFu, v, 0);
        // one u64->f32 per group; per-bucket adds in f32 (err ~1e-7 rel)
        float runf = __ull2float_rn(run_base + (u64)(v - s[j]));

        uint4 q = r[j];
        u32 e0 = q.x & EMASK, e1 = q.y & EMASK, e2 = q.z & EMASK, e3 = q.w & EMASK;
        u32 c0 = q.x >> 24,  c1 = q.y >> 24,  c2 = q.z >> 24,  c3 = q.w >> 24;
        runf += (float)e3; if (c3) contrib += (float)c3 * __logf(runf * INV_FPS_F);
        runf += (float)e2; if (c2) contrib += (float)c2 * __logf(runf * INV_FPS_F);
        runf += (float)e1; if (c1) contrib += (float)c1 * __logf(runf * INV_FPS_F);
        runf += (float)e0; if (c0) contrib += (float)c0 * __logf(runf * INV_FPS_F);

        run_base += (u64)total;
    }

    double t = block_reduce_f64((double)contrib, shd);
    if (tid == 0) {
        atomicAdd(&g_logterm, t);
        __threadfence();
        is_last = (atomicAdd(&g_cnt, 1u) == (u32)gridDim.x - 1u);
    }
    __syncthreads();

    // --- last block: finalize + reset all state for graph replay ---
    if (is_last) {
        for (int j = tid; j < NB; j += THR) g_desc[j] = 0ULL;
        if (tid == 0) {
            double lt = atomicAdd(&g_logterm, 0.0);
            double ev = atomicAdd(&g_evx, 0.0);
            out[0] = (float)sqrt((lt - ev) / (double)n);
            g_logterm = 0.0;
            g_evx = 0.0;
            g_cnt = 0u;
        }
    }
}

// ---------------------------------------------------------------------------
extern "C" void kernel_launch(void* const* d_in, const int* in_sizes, int n_in,
                              void* d_out, int out_size) {
    const float* x   = (const float*)d_in[0];
    const float* tgt = (const float*)d_in[1];
    float* out = (float*)d_out;
    int n = in_sizes[0];

    accum_kernel<<<1184, THR>>>(x, tgt, n);
    scan_kernel<<<NB, THR>>>(out, n);
}

// round 16
// speedup vs baseline: 1.0565x; 1.0565x over previous
#include <cuda_runtime.h>
#include <math.h>

#define T_MAXC 1000000
#define ATHR 256                            // accum block size
#define AWARPS (ATHR / 32)
#define STHR 512                            // scan block size (16 warps -> 4/SMSP)
#define SWARPS (STHR / 32)                  // 16
#define NB 140                              // scan blocks (1/SM, minimal lookback)
#define U4PL 4                              // uint4 per lane
#define U4PW (U4PL * 32)                    // 128 uint4 per warp
#define CHUNK (U4PW * 4 * SWARPS)           // 8192 buckets per block
#define T_PAD (NB * CHUNK)                  // 1146880 (padding stays 0)
#define FPS 2048.0f                         // 2^11 fixed-point scale
#define INV_FPS_F (1.0f / 2048.0f)
#define EMASK 0x00FFFFFFu
#define DESC_FLAG (1ULL << 63)

typedef unsigned long long u64;
typedef unsigned int u32;

// Static device globals (zero at load; every launch restores zeros).
// Packed bucket: bits[0:24) sum(exp x) in 2^-11 fixed point, bits[24:32) event count.
__device__ u32 g_packed[T_PAD];
__device__ volatile u64 g_desc[NB];         // chunk aggregate | DESC_FLAG when valid
__device__ double g_evx;
__device__ double g_logterm;
__device__ u32 g_cnt;

// ---------------------------------------------------------------------------
// Pass 1: one u32 RED per element (sumexp fixed-point + event count packed).
__device__ __forceinline__ void proc(float xv, float tv, float ev, float& evx) {
    int ti = (int)tv;
    ti = min(max(ti, 0), T_MAXC - 1);
    u32 enc = __float2uint_rn(__expf(xv) * FPS) + ((u32)ev << 24);
    atomicAdd(&g_packed[ti], enc);
    if (ev != 0.0f) evx += xv;              // float partial; double at block reduce
}

__global__ void __launch_bounds__(ATHR) accum_kernel(const float* __restrict__ x,
                                                     const float* __restrict__ tgt,
                                                     int n) {
    const float4* x4 = reinterpret_cast<const float4*>(x);
    const float4* t4 = reinterpret_cast<const float4*>(tgt);
    int n8 = n >> 3;
    int stride = gridDim.x * blockDim.x;
    float evx = 0.0f;

    for (int i = blockIdx.x * blockDim.x + threadIdx.x; i < n8; i += stride) {
        float4 xa = __ldcg(&x4[2 * i]);
        float4 xb = __ldcg(&x4[2 * i + 1]);
        float4 t0 = __ldcg(&t4[4 * i]);
        float4 t1 = __ldcg(&t4[4 * i + 1]);
        float4 t2 = __ldcg(&t4[4 * i + 2]);
        float4 t3 = __ldcg(&t4[4 * i + 3]);
        proc(xa.x, t0.x, t0.y, evx);
        proc(xa.y, t0.z, t0.w, evx);
        proc(xa.z, t1.x, t1.y, evx);
        proc(xa.w, t1.z, t1.w, evx);
        proc(xb.x, t2.x, t2.y, evx);
        proc(xb.y, t2.z, t2.w, evx);
        proc(xb.z, t3.x, t3.y, evx);
        proc(xb.w, t3.z, t3.w, evx);
    }
    if (blockIdx.x == 0 && threadIdx.x == 0) {           // scalar tail
        for (int i = n8 * 8; i < n; i++)
            proc(x[i], tgt[2 * i], tgt[2 * i + 1], evx);
    }

    // block reduce (double) -> one global atomic
    __shared__ double shd[AWARPS];
    int lane = threadIdx.x & 31, wid = threadIdx.x >> 5;
    double v = (double)evx;
#pragma unroll
    for (int s = 16; s > 0; s >>= 1) v += __shfl_down_sync(0xFFFFFFFFu, v, s);
    if (lane == 0) shd[wid] = v;
    __syncthreads();
    if (threadIdx.x == 0) {
        double t = 0.0;
#pragma unroll
        for (int w = 0; w < AWARPS; w++) t += shd[w];
        atomicAdd(&g_evx, t);
    }
}

// ---------------------------------------------------------------------------
// Pass 2: single-wave suffix scan. NB=140 blocks (1/SM), 512 threads each
// (4 warps/SMSP for latency hiding). Decoupled aggregate lookback with
// nanosleep backoff. All blocks co-resident -> spin is deadlock-free.
__global__ void __launch_bounds__(STHR, 1) scan_kernel(float* __restrict__ out, int n) {
    __shared__ u64 shw[SWARPS];     // per-warp totals (live whole kernel)
    __shared__ u64 sh2[SWARPS];     // lookback reduction scratch
    __shared__ double shd[SWARPS];
    __shared__ u64 sh_look;
    __shared__ bool is_last;

    int tid = threadIdx.x, b = blockIdx.x;
    int lane = tid & 31, wid = tid >> 5;

    // --- coalesced direct loads: lane k owns uint4 (base + j*32 + k) ---
    uint4* p4 = reinterpret_cast<uint4*>(g_packed);
    int base = b * (CHUNK / 4) + wid * U4PW + lane;
    uint4 r[U4PL];
    u32 s[U4PL];
    u32 local = 0;
#pragma unroll
    for (int j = 0; j < U4PL; j++) {
        r[j] = p4[base + j * 32];
        s[j] = (r[j].x & EMASK) + (r[j].y & EMASK) +
               (r[j].z & EMASK) + (r[j].w & EMASK);
        local += s[j];
    }
#pragma unroll
    for (int j = 0; j < U4PL; j++)
        p4[base + j * 32] = make_uint4(0u, 0u, 0u, 0u);   // re-zero for next launch

    // --- warp totals -> block aggregate -> publish (single u64 word) ---
    u32 lv = local;
#pragma unroll
    for (int st = 16; st > 0; st >>= 1) lv += __shfl_down_sync(0xFFFFFFFFu, lv, st);
    if (lane == 0) shw[wid] = (u64)lv;
    __syncthreads();
    if (tid == 0) {
        u64 t = 0;
#pragma unroll
        for (int w = 0; w < SWARPS; w++) t += shw[w];
        g_desc[b] = t | DESC_FLAG;
    }

    // --- lookback: thread t spin-reads aggregate of chunk b+1+t (parallel,
    //     with backoff so 19K spinners don't hammer the 18 hot L2 lines) ---
    u64 lb = 0;
    int jj = b + 1 + tid;
    if (jj < NB) {
        u64 d = g_desc[jj];
        while (!(d & DESC_FLAG)) { __nanosleep(40); d = g_desc[jj]; }
        lb = d & ~DESC_FLAG;
    }
#pragma unroll
    for (int st = 16; st > 0; st >>= 1) lb += __shfl_down_sync(0xFFFFFFFFu, lb, st);
    if (lane == 0) sh2[wid] = lb;
    __syncthreads();
    if (tid == 0) {
        u64 t = 0;
#pragma unroll
        for (int w = 0; w < SWARPS; w++) t += sh2[w];
        sh_look = t;
    }
    __syncthreads();

    // --- exclusive suffix base for this warp ---
    u64 woff = 0;
#pragma unroll
    for (int w = 0; w < SWARPS; w++)
        if (w > wid) woff += shw[w];
    u64 run_base = sh_look + woff;   // sum of everything after this warp's range

    // --- per-j warp suffix scans interleaved with log walk (float run) ---
    float contrib = 0.0f;
#pragma unroll
    for (int j = U4PL - 1; j >= 0; j--) {
        u32 v = s[j];
#pragma unroll
        for (int st = 1; st < 32; st <<= 1) {
            u32 o = __shfl_down_sync(0xFFFFFFFFu, v, st);
            if (lane + st < 32) v += o;
        }
        u32 total = __shfl_sync(0xFFFFFFFFu, v, 0);
        // one u64->f32 per group; per-bucket adds in f32 (err ~1e-7 rel)
        float runf = __ull2float_rn(run_base + (u64)(v - s[j]));

        uint4 q = r[j];
        u32 e0 = q.x & EMASK, e1 = q.y & EMASK, e2 = q.z & EMASK, e3 = q.w & EMASK;
        u32 c0 = q.x >> 24,  c1 = q.y >> 24,  c2 = q.z >> 24,  c3 = q.w >> 24;
        runf += (float)e3; if (c3) contrib += (float)c3 * __logf(runf * INV_FPS_F);
        runf += (float)e2; if (c2) contrib += (float)c2 * __logf(runf * INV_FPS_F);
        runf += (float)e1; if (c1) contrib += (float)c1 * __logf(runf * INV_FPS_F);
        runf += (float)e0; if (c0) contrib += (float)c0 * __logf(runf * INV_FPS_F);

        run_base += (u64)total;
    }

    // block reduce contrib (double)
    double cv = (double)contrib;
#pragma unroll
    for (int st = 16; st > 0; st >>= 1) cv += __shfl_down_sync(0xFFFFFFFFu, cv, st);
    if (lane == 0) shd[wid] = cv;
    __syncthreads();
    if (tid == 0) {
        double t = 0.0;
#pragma unroll
        for (int w = 0; w < SWARPS; w++) t += shd[w];
        atomicAdd(&g_logterm, t);
        __threadfence();
        is_last = (atomicAdd(&g_cnt, 1u) == (u32)gridDim.x - 1u);
    }
    __syncthreads();

    // --- last block: finalize + reset all state for graph replay ---
    if (is_last) {
        if (tid < NB) g_desc[tid] = 0ULL;
        if (tid == 0) {
            double lt = atomicAdd(&g_logterm, 0.0);
            double ev = atomicAdd(&g_evx, 0.0);
            out[0] = (float)sqrt((lt - ev) / (double)n);
            g_logterm = 0.0;
            g_evx = 0.0;
            g_cnt = 0u;
        }
    }
}

// ---------------------------------------------------------------------------
extern "C" void kernel_launch(void* const* d_in, const int* in_sizes, int n_in,
                              void* d_out, int out_size) {
    const float* x   = (const float*)d_in[0];
    const float* tgt = (const float*)d_in[1];
    float* out = (float*)d_out;
    int n = in_sizes[0];

    accum_kernel<<<1184, ATHR>>>(x, tgt, n);
    scan_kernel<<<NB, STHR>>>(out, n);
}